// round 15
// baseline (speedup 1.0000x reference)
#include <cuda_runtime.h>
#include <cuda_fp16.h>
#include <math.h>
#include <stdint.h>

// ---------------------------------------------------------------------------
// SwitchHeadCore: B=2,S=2048,D=1024,H=8,E=4,K=2,DH=128
// fp16 m16n8k16 + ldmatrix + cp.async.  Gate-folding vall epilogue (no yall),
// fp32 blocked router, merged conv, attention kv-tile 128 double-buffered.
// ---------------------------------------------------------------------------

#define B_ 2
#define S_ 2048
#define D_ 1024
#define H_ 8
#define E_ 4
#define DH_ 128
#define TOK_ (B_ * S_)              // 4096
#define GE_ (H_ * E_)               // 32
#define KEXP_ 4096                  // H*E*DH

__device__ __align__(16) __half g_q[TOK_ * D_];     // [B,H,S,DH]
__device__ __align__(16) __half g_k[TOK_ * D_];
__device__ __align__(16) __half g_v[TOK_ * D_];     // [B,H,S,DH]
__device__ __align__(16) __half g_vT[TOK_ * D_];    // [B,H,DH,S]
__device__ __align__(16) float  g_res[TOK_ * D_];   // fp32
__device__ float g_gv[TOK_ * GE_];
__device__ float g_go[TOK_ * GE_];
__device__ __align__(16) __half g_aexp[(size_t)TOK_ * KEXP_];
__device__ __align__(16) __half g_wvT[(size_t)KEXP_ * D_];    // [(h,dh,e), d]
__device__ __align__(16) __half g_woT[(size_t)D_ * KEXP_];    // [o, (h,e,dh)]
__device__ __align__(16) __half g_qc[TOK_ * D_];
__device__ __align__(16) __half g_kc[TOK_ * D_];
__device__ __align__(16) __half g_vc[TOK_ * D_];
__device__ __align__(16) __half g_wqc[D_ * D_];
__device__ __align__(16) __half g_wkc[D_ * D_];

// ============================ helpers ======================================
__device__ __forceinline__ void mma_f16(float* d, const uint32_t* a, const uint32_t* b) {
    asm volatile(
        "mma.sync.aligned.m16n8k16.row.col.f32.f16.f16.f32 "
        "{%0,%1,%2,%3}, {%4,%5,%6,%7}, {%8,%9}, {%0,%1,%2,%3};\n"
        : "+f"(d[0]), "+f"(d[1]), "+f"(d[2]), "+f"(d[3])
        : "r"(a[0]), "r"(a[1]), "r"(a[2]), "r"(a[3]), "r"(b[0]), "r"(b[1]));
}
__device__ __forceinline__ void ldsm4(uint32_t addr, uint32_t* r) {
    asm volatile("ldmatrix.sync.aligned.m8n8.x4.shared.b16 {%0,%1,%2,%3}, [%4];"
        : "=r"(r[0]), "=r"(r[1]), "=r"(r[2]), "=r"(r[3]) : "r"(addr));
}
__device__ __forceinline__ uint32_t smem_u32(const void* p) {
    uint32_t a;
    asm("{ .reg .u64 t; cvta.to.shared.u64 t, %1; cvt.u32.u64 %0, t; }" : "=r"(a) : "l"(p));
    return a;
}
__device__ __forceinline__ uint32_t pack_h2(float x, float y) {
    __half2 h = __floats2half2_rn(x, y);
    return *(uint32_t*)&h;
}
#define CP16(dst, src) \
    asm volatile("cp.async.cg.shared.global [%0], [%1], 16;" :: "r"(dst), "l"(src))
#define CP_COMMIT() asm volatile("cp.async.commit_group;")
#define CP_WAIT1() asm volatile("cp.async.wait_group 1;")
#define CP_WAIT0() asm volatile("cp.async.wait_group 0;")

// ============================ blocked fp32 router ==========================
#define RT_ 32
#define RXP_ 1033
#define RSMEM_BYTES ((RT_ * RXP_ + RT_ * GE_) * 4)   // 136320

__global__ __launch_bounds__(256) void router_kernel(const float* __restrict__ k_src,
                                                     const float* __restrict__ q_src,
                                                     const float* __restrict__ sel_v,
                                                     const float* __restrict__ sel_o) {
    extern __shared__ float rsm[];
    float* xs = rsm;
    float* sg = rsm + RT_ * RXP_;

    int z = blockIdx.y;
    const float* xsrc = z ? q_src : k_src;
    const float* sel  = z ? sel_o : sel_v;
    float* gout       = z ? g_go  : g_gv;

    int t0 = blockIdx.x * RT_;
    int tid = threadIdx.x;

    for (int i = tid; i < RT_ * (D_ / 4); i += 256) {
        int r = i >> 8, c4 = i & 255;
        float4 v = ((const float4*)(xsrc + (size_t)(t0 + r) * D_))[c4];
        float* dst = xs + r * RXP_ + c4 * 4;
        dst[0] = v.x; dst[1] = v.y; dst[2] = v.z; dst[3] = v.w;
    }
    __syncthreads();

    int g = tid >> 3, slot = tid & 7;
    const float* w = sel + (size_t)g * D_;
    const float* x0 = xs + (slot * 4 + 0) * RXP_;
    const float* x1 = xs + (slot * 4 + 1) * RXP_;
    const float* x2 = xs + (slot * 4 + 2) * RXP_;
    const float* x3 = xs + (slot * 4 + 3) * RXP_;
    float s0 = 0.f, s1 = 0.f, s2 = 0.f, s3 = 0.f;
    #pragma unroll 4
    for (int d = 0; d < D_; d++) {
        float sv = w[d];
        s0 += x0[d] * sv;
        s1 += x1[d] * sv;
        s2 += x2[d] * sv;
        s3 += x3[d] * sv;
    }
    sg[(slot * 4 + 0) * GE_ + g] = s0;
    sg[(slot * 4 + 1) * GE_ + g] = s1;
    sg[(slot * 4 + 2) * GE_ + g] = s2;
    sg[(slot * 4 + 3) * GE_ + g] = s3;
    __syncthreads();

    int t = tid >> 3, h = tid & 7;
    float vals[4];
    #pragma unroll
    for (int e = 0; e < 4; e++)
        vals[e] = 1.f / (1.f + __expf(-sg[t * GE_ + h * 4 + e]));
    int i1 = 0;
    #pragma unroll
    for (int e = 1; e < 4; e++) if (vals[e] > vals[i1]) i1 = e;
    int i2 = -1;
    #pragma unroll
    for (int e = 0; e < 4; e++) {
        if (e == i1) continue;
        if (i2 < 0 || vals[e] > vals[i2]) i2 = e;
    }
    #pragma unroll
    for (int e = 0; e < 4; e++)
        gout[(size_t)(t0 + t) * GE_ + h * 4 + e] = (e == i1 || e == i2) ? vals[e] : 0.f;
}

// ============================ merged convert (fp32 -> fp16) ================
// segments: q_src, k_src, v_src (1M float4 each), Wq, Wk (256K float4 each)
#define CVA_ (TOK_ * D_ / 4)    // 1048576
#define CVW_ (D_ * D_ / 4)      // 262144
#define CVTOT_ (3 * CVA_ + 2 * CVW_)

__global__ void conv_all_kernel(const float* __restrict__ q_src,
                                const float* __restrict__ k_src,
                                const float* __restrict__ v_src,
                                const float* __restrict__ Wq,
                                const float* __restrict__ Wk) {
    int i = blockIdx.x * blockDim.x + threadIdx.x;
    if (i >= CVTOT_) return;
    const float* src;
    __half* dst;
    int j = i;
    if (j < CVA_) { src = q_src; dst = g_qc; }
    else if ((j -= CVA_) < CVA_) { src = k_src; dst = g_kc; }
    else if ((j -= CVA_) < CVA_) { src = v_src; dst = g_vc; }
    else if ((j -= CVA_) < CVW_) { src = Wq; dst = g_wqc; }
    else { j -= CVW_; src = Wk; dst = g_wkc; }
    float4 v = ((const float4*)src)[j];
    ((__half2*)dst)[j * 2 + 0] = __floats2half2_rn(v.x, v.y);
    ((__half2*)dst)[j * 2 + 1] = __floats2half2_rn(v.z, v.w);
}

// ============================ transpose Wv (fp32 -> fp16, (h,dh,e) rows) ===
// Wv [H,E,D,DH]; z = h*4+e; dst row = h*512 + dh*4 + e, dst[row*D + d].
__global__ void transpose_wv_kernel(const float* __restrict__ src) {
    __shared__ float tile[32][33];
    int z = blockIdx.z;
    int h = z >> 2, e = z & 3;
    const float* s = src + (size_t)z * D_ * DH_;
    int r0 = blockIdx.y * 32, c0 = blockIdx.x * 32;   // r = d, c = dh
    int x = threadIdx.x, y = threadIdx.y;
    #pragma unroll
    for (int i = 0; i < 32; i += 8)
        tile[y + i][x] = s[(size_t)(r0 + y + i) * DH_ + c0 + x];
    __syncthreads();
    #pragma unroll
    for (int i = 0; i < 32; i += 8) {
        int dh = c0 + y + i;
        g_wvT[(size_t)(h * 512 + dh * 4 + e) * D_ + r0 + x] = __float2half_rn(tile[x][y + i]);
    }
}

// ============================ transpose (fp32 src -> fp16 dst) =============
__global__ void transpose_kernel(const float* __restrict__ src, __half* __restrict__ dst,
                                 int R, int C) {
    __shared__ float tile[32][33];
    size_t zo = (size_t)blockIdx.z * R * C;
    src += zo; dst += zo;
    int r0 = blockIdx.y * 32, c0 = blockIdx.x * 32;
    int x = threadIdx.x, y = threadIdx.y;
    #pragma unroll
    for (int i = 0; i < 32; i += 8)
        tile[y + i][x] = src[(size_t)(r0 + y + i) * C + c0 + x];
    __syncthreads();
    #pragma unroll
    for (int i = 0; i < 32; i += 8)
        dst[(size_t)(c0 + y + i) * R + r0 + x] = __float2half_rn(tile[x][y + i]);
}

// ============================ transpose V (fp16) ===========================
__global__ void transpose_v_kernel() {
    __shared__ __half tile[32][33];
    int z = blockIdx.z;
    const __half* src = g_v + (size_t)z * S_ * DH_;
    __half* dst = g_vT + (size_t)z * S_ * DH_;
    int s0 = blockIdx.y * 32, d0 = blockIdx.x * 32;
    int x = threadIdx.x, y = threadIdx.y;
    #pragma unroll
    for (int i = 0; i < 32; i += 8)
        tile[y + i][x] = src[(size_t)(s0 + y + i) * DH_ + d0 + x];
    __syncthreads();
    #pragma unroll
    for (int i = 0; i < 32; i += 8)
        dst[(size_t)(d0 + y + i) * S_ + s0 + x] = tile[x][y + i];
}

// ============================ gated expand (O), fp16 out ===================
__global__ __launch_bounds__(256) void expand_kernel() {
    int idx = blockIdx.x * 256 + threadIdx.x;
    int dh4 = idx & 31;
    int he = (idx >> 5) & 31;
    int t = idx >> 10;
    int h = he >> 2;
    int b = t >> 11, s = t & (S_ - 1);
    float g = g_go[(size_t)t * GE_ + he];
    float4 r = *(const float4*)&g_res[(((size_t)b * H_ + h) * S_ + s) * DH_ + dh4 * 4];
    __half2* dst = (__half2*)&g_aexp[(size_t)t * KEXP_ + he * 128 + dh4 * 4];
    dst[0] = __floats2half2_rn(r.x * g, r.y * g);
    dst[1] = __floats2half2_rn(r.z * g, r.w * g);
}

// ============================ fp16 mma GEMM (cp.async + ldmatrix) ==========
// MODE 0: fp32 row-major C.  MODE 1: qk merged, fp16 C [B,H,S,DH].
// MODE 3: vall w/ gate-folding epilogue: B rows ordered (h,dh,e);
//         out = sum_e gv[t,h,e]*acc -> g_v [B,H,S,DH] fp16.
#define PADH_ 36
#define ABUF_ (128 * PADH_)
#define BBUF_ (256 * PADH_)
#define STG_W (ABUF_ + BBUF_)
#define GSMEM_BYTES (3 * STG_W * 4)     // 165888

template<int MODE>
__global__ __launch_bounds__(512) void gemm_f16(const __half* __restrict__ A,
                                                const __half* __restrict__ B,
                                                void* __restrict__ Cv,
                                                int Ktot, int ldc, float alpha,
                                                const __half* __restrict__ A2,
                                                const __half* __restrict__ B2,
                                                void* __restrict__ C2v) {
    extern __shared__ __align__(16) uint32_t dsm[];
    uint32_t sbase = smem_u32(dsm);

    int tid = threadIdx.x;
    int wid = tid >> 5;
    int lane = tid & 31;
    int m0 = blockIdx.y * 128, n0 = blockIdx.x * 256;
    int m0w = (wid >> 2) * 32, n0w = (wid & 3) * 64;

    void* Cp = Cv;
    if (MODE == 1 && blockIdx.z == 1) { A = A2; B = B2; Cp = C2v; }

    int ar0 = tid >> 3, ao0 = (tid & 7) * 8;
    int aS1 = tid + 512;
    int ar1 = aS1 >> 3, ao1 = (aS1 & 7) * 8;
    const __half* Asrc0 = A + (size_t)(m0 + ar0) * Ktot + ao0;
    const __half* Asrc1 = A + (size_t)(m0 + ar1) * Ktot + ao1;
    uint32_t aDst0 = (uint32_t)(ar0 * PADH_ + (ao0 >> 1)) * 4;
    uint32_t aDst1 = (uint32_t)(ar1 * PADH_ + (ao1 >> 1)) * 4;
    const __half* Bsrc[4];
    uint32_t bDst[4];
    #pragma unroll
    for (int j = 0; j < 4; j++) {
        int s = tid + 512 * j;
        int brr = s >> 3, bo = (s & 7) * 8;
        Bsrc[j] = B + (size_t)(n0 + brr) * Ktot + bo;
        bDst[j] = (uint32_t)(ABUF_ + brr * PADH_ + (bo >> 1)) * 4;
    }

    float acc[2][8][4];
    #pragma unroll
    for (int i = 0; i < 2; i++)
        #pragma unroll
        for (int j = 0; j < 8; j++)
            #pragma unroll
            for (int c = 0; c < 4; c++) acc[i][j][c] = 0.f;

    int KT = Ktot >> 6;

    auto copyTile = [&](int kt, int stg) {
        uint32_t so = sbase + (uint32_t)(stg * STG_W * 4);
        int ko = kt * 64;
        CP16(so + aDst0, Asrc0 + ko);
        CP16(so + aDst1, Asrc1 + ko);
        #pragma unroll
        for (int j = 0; j < 4; j++)
            CP16(so + bDst[j], Bsrc[j] + ko);
        CP_COMMIT();
    };

    copyTile(0, 0);
    copyTile(1, 1);

    int g8 = lane >> 3, l8 = lane & 7;
    uint32_t aRow = (uint32_t)(m0w + (g8 & 1) * 8 + l8);
    uint32_t aCo  = (uint32_t)((g8 >> 1) * 4);
    uint32_t bRow = (uint32_t)(n0w + (g8 >> 1) * 8 + l8);
    uint32_t bCo  = (uint32_t)((g8 & 1) * 4);

    for (int kt = 0; kt < KT; kt++) {
        if (kt + 1 < KT) CP_WAIT1(); else CP_WAIT0();
        __syncthreads();

        uint32_t AsAddr = sbase + (uint32_t)((kt % 3) * STG_W * 4);
        uint32_t BsAddr = AsAddr + (uint32_t)(ABUF_ * 4);
        #pragma unroll
        for (int ks = 0; ks < 4; ks++) {
            uint32_t kb = (uint32_t)(ks * 8);
            uint32_t a[2][4], b[8][2];
            #pragma unroll
            for (int mi = 0; mi < 2; mi++)
                ldsm4(AsAddr + ((aRow + mi * 16) * PADH_ + kb + aCo) * 4, a[mi]);
            #pragma unroll
            for (int p = 0; p < 4; p++) {
                uint32_t r4v[4];
                ldsm4(BsAddr + ((bRow + p * 16) * PADH_ + kb + bCo) * 4, r4v);
                b[2 * p][0] = r4v[0]; b[2 * p][1] = r4v[1];
                b[2 * p + 1][0] = r4v[2]; b[2 * p + 1][1] = r4v[3];
            }
            #pragma unroll
            for (int mi = 0; mi < 2; mi++)
                #pragma unroll
                for (int ni = 0; ni < 8; ni++)
                    mma_f16(acc[mi][ni], a[mi], b[ni]);
        }

        if (kt + 2 < KT) copyTile(kt + 2, (kt + 2) % 3);
    }

    int r4 = lane >> 2, c4 = lane & 3;
    #pragma unroll
    for (int mi = 0; mi < 2; mi++) {
        #pragma unroll
        for (int half_m = 0; half_m < 2; half_m++) {
            int m = m0 + m0w + mi * 16 + half_m * 8 + r4;
            int bb = m >> 11, ss = m & (S_ - 1);
            #pragma unroll
            for (int ni = 0; ni < 8; ni++) {
                int n = n0 + n0w + ni * 8 + c4 * 2;
                float ox = acc[mi][ni][half_m * 2 + 0] * alpha;
                float oy = acc[mi][ni][half_m * 2 + 1] * alpha;
                if (MODE == 1) {
                    int h = n >> 7, dh = n & 127;
                    *(__half2*)((__half*)Cp + (((size_t)bb * H_ + h) * S_ + ss) * DH_ + dh) =
                        __floats2half2_rn(ox, oy);
                } else if (MODE == 3) {
                    int h = n >> 9, dh = (n >> 2) & 127, e = n & 3;
                    const float* gp = g_gv + (size_t)m * GE_ + h * 4;
                    float part = ox * gp[e] + oy * gp[e + 1];
                    part += __shfl_xor_sync(0xffffffffu, part, 1);
                    if ((c4 & 1) == 0)
                        *((__half*)Cp + (((size_t)bb * H_ + h) * S_ + ss) * DH_ + dh) =
                            __float2half_rn(part);
                } else {
                    *(float2*)((float*)Cp + (size_t)m * ldc + n) = make_float2(ox, oy);
                }
            }
        }
    }
}

// ============================ fp16 flash attention (ldmatrix) ==============
#define APH_ 68
#define ATILE_ (128 * APH_)
#define QS_OFF 0
#define KS_OFF ATILE_
#define VT_OFF (3 * ATILE_)
#define PS_OFF (5 * ATILE_)
#define ATTN_SMEM (6 * ATILE_ * 4)      // 208896

__global__ __launch_bounds__(256) void attn_tc_kernel() {
    extern __shared__ __align__(16) uint32_t asm_[];
    uint32_t sbase = smem_u32(asm_);
    uint32_t* Qs = asm_ + QS_OFF;
    uint32_t* Ps = asm_ + PS_OFF;
    uint32_t QsAddr = sbase;
    uint32_t PsAddr = sbase + (uint32_t)(PS_OFF * 4);

    int bh = blockIdx.y;
    int q0 = blockIdx.x * 128;
    const __half* Qg = g_q + (size_t)bh * S_ * DH_;
    const __half* Kg = g_k + (size_t)bh * S_ * DH_;
    const __half* VTg = g_vT + (size_t)bh * S_ * DH_;

    int tid = threadIdx.x;
    int wid = tid >> 5;
    int lane = tid & 31;
    int r4 = lane >> 2, c4 = lane & 3;
    int m0w = wid * 16;
    int g8 = lane >> 3, l8 = lane & 7;
    uint32_t aRow = (uint32_t)(m0w + (g8 & 1) * 8 + l8);
    uint32_t aCo  = (uint32_t)((g8 >> 1) * 4);
    uint32_t bRow = (uint32_t)((g8 >> 1) * 8 + l8);
    uint32_t bCo  = (uint32_t)((g8 & 1) * 4);

    for (int i = tid; i < 2048; i += 256) {
        int r = i >> 4, w = i & 15;
        *(uint4*)&Qs[r * APH_ + w * 4] = *(const uint4*)(Qg + (size_t)(q0 + r) * DH_ + w * 8);
    }

    auto copyKV = [&](int j0, int buf) {
        uint32_t ks = sbase + (uint32_t)((KS_OFF + buf * ATILE_) * 4);
        uint32_t vs = sbase + (uint32_t)((VT_OFF + buf * ATILE_) * 4);
        #pragma unroll
        for (int jj = 0; jj < 8; jj++) {
            int i = tid + 256 * jj;
            int r = i >> 4, w = i & 15;
            CP16(ks + (uint32_t)(r * APH_ + w * 4) * 4, Kg + (size_t)(j0 + r) * DH_ + w * 8);
            CP16(vs + (uint32_t)(r * APH_ + w * 4) * 4, VTg + (size_t)r * S_ + j0 + w * 8);
        }
        CP_COMMIT();
    };

    copyKV(0, 0);

    float o[16][4];
    #pragma unroll
    for (int ni = 0; ni < 16; ni++)
        #pragma unroll
        for (int c = 0; c < 4; c++) o[ni][c] = 0.f;
    float mA = -1e30f, mB = -1e30f, lA = 0.f, lB = 0.f;

    for (int it = 0; it < S_ / 128; it++) {
        int buf = it & 1;
        __syncthreads();
        if (it + 1 < S_ / 128) {
            copyKV((it + 1) * 128, buf ^ 1);
            CP_WAIT1();
        } else {
            CP_WAIT0();
        }
        __syncthreads();

        uint32_t KsAddr = sbase + (uint32_t)((KS_OFF + buf * ATILE_) * 4);
        uint32_t VtAddr = sbase + (uint32_t)((VT_OFF + buf * ATILE_) * 4);

        float sf[16][4];
        #pragma unroll
        for (int ni = 0; ni < 16; ni++)
            #pragma unroll
            for (int c = 0; c < 4; c++) sf[ni][c] = 0.f;

        #pragma unroll
        for (int ks = 0; ks < 8; ks++) {
            uint32_t kb = (uint32_t)(ks * 8);
            uint32_t a[4], b[16][2];
            ldsm4(QsAddr + (aRow * APH_ + kb + aCo) * 4, a);
            #pragma unroll
            for (int p = 0; p < 8; p++) {
                uint32_t r4v[4];
                ldsm4(KsAddr + ((bRow + p * 16) * APH_ + kb + bCo) * 4, r4v);
                b[2 * p][0] = r4v[0]; b[2 * p][1] = r4v[1];
                b[2 * p + 1][0] = r4v[2]; b[2 * p + 1][1] = r4v[3];
            }
            #pragma unroll
            for (int ni = 0; ni < 16; ni++)
                mma_f16(sf[ni], a, b[ni]);
        }

        float mxA = -1e30f, mxB = -1e30f;
        #pragma unroll
        for (int ni = 0; ni < 16; ni++) {
            mxA = fmaxf(mxA, fmaxf(sf[ni][0], sf[ni][1]));
            mxB = fmaxf(mxB, fmaxf(sf[ni][2], sf[ni][3]));
        }
        mxA = fmaxf(mxA, __shfl_xor_sync(0xffffffffu, mxA, 1));
        mxA = fmaxf(mxA, __shfl_xor_sync(0xffffffffu, mxA, 2));
        mxB = fmaxf(mxB, __shfl_xor_sync(0xffffffffu, mxB, 1));
        mxB = fmaxf(mxB, __shfl_xor_sync(0xffffffffu, mxB, 2));
        float mnA = fmaxf(mA, mxA), mnB = fmaxf(mB, mxB);
        float scA = __expf(mA - mnA), scB = __expf(mB - mnB);
        float sA = 0.f, sB = 0.f;
        int prA = (m0w + r4) * APH_;
        int prB = prA + 8 * APH_;
        #pragma unroll
        for (int ni = 0; ni < 16; ni++) {
            float e0 = __expf(sf[ni][0] - mnA);
            float e1 = __expf(sf[ni][1] - mnA);
            float e2 = __expf(sf[ni][2] - mnB);
            float e3 = __expf(sf[ni][3] - mnB);
            sA += e0 + e1; sB += e2 + e3;
            int cw = ni * 4 + c4;
            Ps[prA + cw] = pack_h2(e0, e1);
            Ps[prB + cw] = pack_h2(e2, e3);
        }
        sA += __shfl_xor_sync(0xffffffffu, sA, 1);
        sA += __shfl_xor_sync(0xffffffffu, sA, 2);
        sB += __shfl_xor_sync(0xffffffffu, sB, 1);
        sB += __shfl_xor_sync(0xffffffffu, sB, 2);
        lA = lA * scA + sA; lB = lB * scB + sB;
        mA = mnA; mB = mnB;
        #pragma unroll
        for (int ni = 0; ni < 16; ni++) {
            o[ni][0] *= scA; o[ni][1] *= scA;
            o[ni][2] *= scB; o[ni][3] *= scB;
        }
        __syncwarp();

        #pragma unroll
        for (int ks = 0; ks < 8; ks++) {
            uint32_t kb = (uint32_t)(ks * 8);
            uint32_t a[4], b[16][2];
            ldsm4(PsAddr + (aRow * APH_ + kb + aCo) * 4, a);
            #pragma unroll
            for (int p = 0; p < 8; p++) {
                uint32_t r4v[4];
                ldsm4(VtAddr + ((bRow + p * 16) * APH_ + kb + bCo) * 4, r4v);
                b[2 * p][0] = r4v[0]; b[2 * p][1] = r4v[1];
                b[2 * p + 1][0] = r4v[2]; b[2 * p + 1][1] = r4v[3];
            }
            #pragma unroll
            for (int ni = 0; ni < 16; ni++)
                mma_f16(o[ni], a, b[ni]);
        }
    }

    float invA = 1.f / lA, invB = 1.f / lB;
    int rA = q0 + m0w + r4;
    float* OgA = g_res + (size_t)bh * S_ * DH_ + (size_t)rA * DH_;
    float* OgB = OgA + 8 * DH_;
    #pragma unroll
    for (int ni = 0; ni < 16; ni++) {
        int cc = ni * 8 + c4 * 2;
        float2 oa, ob;
        oa.x = o[ni][0] * invA; oa.y = o[ni][1] * invA;
        ob.x = o[ni][2] * invB; ob.y = o[ni][3] * invB;
        *(float2*)(OgA + cc) = oa;
        *(float2*)(OgB + cc) = ob;
    }
}

// ---------------------------------------------------------------------------
extern "C" void kernel_launch(void* const* d_in, const int* in_sizes, int n_in,
                              void* d_out, int out_size) {
    const float* q_src = (const float*)d_in[0];
    const float* k_src = (const float*)d_in[1];
    const float* v_src = (const float*)d_in[2];
    const float* Wq    = (const float*)d_in[3];
    const float* Wk    = (const float*)d_in[4];
    const float* Wv    = (const float*)d_in[5];
    const float* Wo    = (const float*)d_in[6];
    const float* sel_v = (const float*)d_in[7];
    const float* sel_o = (const float*)d_in[8];
    float* outp = (float*)d_out;

    cudaFuncSetAttribute(attn_tc_kernel, cudaFuncAttributeMaxDynamicSharedMemorySize, ATTN_SMEM);
    cudaFuncSetAttribute(gemm_f16<0>, cudaFuncAttributeMaxDynamicSharedMemorySize, GSMEM_BYTES);
    cudaFuncSetAttribute(gemm_f16<1>, cudaFuncAttributeMaxDynamicSharedMemorySize, GSMEM_BYTES);
    cudaFuncSetAttribute(gemm_f16<3>, cudaFuncAttributeMaxDynamicSharedMemorySize, GSMEM_BYTES);
    cudaFuncSetAttribute(router_kernel, cudaFuncAttributeMaxDynamicSharedMemorySize, RSMEM_BYTES);

    __half *gq, *gk, *gv, *gaexp, *gwvT, *gwoT, *gqc, *gkc, *gvc, *gwqc, *gwkc;
    cudaGetSymbolAddress((void**)&gq, g_q);
    cudaGetSymbolAddress((void**)&gk, g_k);
    cudaGetSymbolAddress((void**)&gv, g_v);
    cudaGetSymbolAddress((void**)&gaexp, g_aexp);
    cudaGetSymbolAddress((void**)&gwvT, g_wvT);
    cudaGetSymbolAddress((void**)&gwoT, g_woT);
    cudaGetSymbolAddress((void**)&gqc, g_qc);
    cudaGetSymbolAddress((void**)&gkc, g_kc);
    cudaGetSymbolAddress((void**)&gvc, g_vc);
    cudaGetSymbolAddress((void**)&gwqc, g_wqc);
    cudaGetSymbolAddress((void**)&gwkc, g_wkc);

    const float scale = 0.29730177875068026f;  // 128^-0.25

    router_kernel<<<dim3(TOK_ / RT_, 2), 256, RSMEM_BYTES>>>(k_src, q_src, sel_v, sel_o);

    conv_all_kernel<<<(CVTOT_ + 255) / 256, 256>>>(q_src, k_src, v_src, Wq, Wk);

    // Wv [H,E,D,DH] -> wvT rows (h,dh,e); Wo flat -> woT [o,(h,e,dh)]
    transpose_wv_kernel<<<dim3(DH_ / 32, D_ / 32, GE_), dim3(32, 8)>>>(Wv);
    transpose_kernel<<<dim3(D_ / 32, KEXP_ / 32, 1), dim3(32, 8)>>>(Wo, gwoT, KEXP_, D_);

    // merged q/k projections: M=4096, N=1024, K=1024; z=0 -> q, z=1 -> k
    gemm_f16<1><<<dim3(D_ / 256, TOK_ / 128, 2), 512, GSMEM_BYTES>>>(
        gqc, gwqc, gq, D_, 0, scale, gkc, gwkc, gk);

    // gated V: M=4096, N=4096 (h,dh,e), K=1024 -> g_v fp16 directly
    gemm_f16<3><<<dim3(KEXP_ / 256, TOK_ / 128), 512, GSMEM_BYTES>>>(
        gvc, gwvT, gv, D_, 0, 1.0f, nullptr, nullptr, nullptr);
    transpose_v_kernel<<<dim3(DH_ / 32, S_ / 32, B_ * H_), dim3(32, 8)>>>();

    attn_tc_kernel<<<dim3(S_ / 128, B_ * H_), 256, ATTN_SMEM>>>();

    expand_kernel<<<TOK_ * GE_ * 32 / 256, 256>>>();
    // out: M=4096, N=1024, K=4096 -> fp32
    gemm_f16<0><<<dim3(D_ / 256, TOK_ / 128), 512, GSMEM_BYTES>>>(
        gaexp, gwoT, outp, KEXP_, D_, 1.0f, nullptr, nullptr, nullptr);
}

// round 16
// speedup vs baseline: 1.0130x; 1.0130x over previous
#include <cuda_runtime.h>
#include <cuda_fp16.h>
#include <math.h>
#include <stdint.h>

// ---------------------------------------------------------------------------
// SwitchHeadCore: B=2,S=2048,D=1024,H=8,E=4,K=2,DH=128
// fp16 m16n8k16 + ldmatrix(+trans) + cp.async.  Gate-folding vall epilogue,
// gated-expansion attention epilogue (no res/expand), fp32 blocked router.
// ---------------------------------------------------------------------------

#define B_ 2
#define S_ 2048
#define D_ 1024
#define H_ 8
#define E_ 4
#define DH_ 128
#define TOK_ (B_ * S_)              // 4096
#define GE_ (H_ * E_)               // 32
#define KEXP_ 4096                  // H*E*DH

__device__ __align__(16) __half g_q[TOK_ * D_];     // [B,H,S,DH]
__device__ __align__(16) __half g_k[TOK_ * D_];
__device__ __align__(16) __half g_v[TOK_ * D_];     // [B,H,S,DH]
__device__ float g_gv[TOK_ * GE_];
__device__ float g_go[TOK_ * GE_];
__device__ __align__(16) __half g_aexp[(size_t)TOK_ * KEXP_];
__device__ __align__(16) __half g_wvT[(size_t)KEXP_ * D_];    // [(h,dh,e), d]
__device__ __align__(16) __half g_woT[(size_t)D_ * KEXP_];    // [o, (h,e,dh)]
__device__ __align__(16) __half g_qc[TOK_ * D_];
__device__ __align__(16) __half g_kc[TOK_ * D_];
__device__ __align__(16) __half g_vc[TOK_ * D_];
__device__ __align__(16) __half g_wqc[D_ * D_];
__device__ __align__(16) __half g_wkc[D_ * D_];

// ============================ helpers ======================================
__device__ __forceinline__ void mma_f16(float* d, const uint32_t* a, const uint32_t* b) {
    asm volatile(
        "mma.sync.aligned.m16n8k16.row.col.f32.f16.f16.f32 "
        "{%0,%1,%2,%3}, {%4,%5,%6,%7}, {%8,%9}, {%0,%1,%2,%3};\n"
        : "+f"(d[0]), "+f"(d[1]), "+f"(d[2]), "+f"(d[3])
        : "r"(a[0]), "r"(a[1]), "r"(a[2]), "r"(a[3]), "r"(b[0]), "r"(b[1]));
}
__device__ __forceinline__ void ldsm4(uint32_t addr, uint32_t* r) {
    asm volatile("ldmatrix.sync.aligned.m8n8.x4.shared.b16 {%0,%1,%2,%3}, [%4];"
        : "=r"(r[0]), "=r"(r[1]), "=r"(r[2]), "=r"(r[3]) : "r"(addr));
}
__device__ __forceinline__ void ldsm4t(uint32_t addr, uint32_t* r) {
    asm volatile("ldmatrix.sync.aligned.m8n8.x4.trans.shared.b16 {%0,%1,%2,%3}, [%4];"
        : "=r"(r[0]), "=r"(r[1]), "=r"(r[2]), "=r"(r[3]) : "r"(addr));
}
__device__ __forceinline__ uint32_t smem_u32(const void* p) {
    uint32_t a;
    asm("{ .reg .u64 t; cvta.to.shared.u64 t, %1; cvt.u32.u64 %0, t; }" : "=r"(a) : "l"(p));
    return a;
}
__device__ __forceinline__ uint32_t pack_h2(float x, float y) {
    __half2 h = __floats2half2_rn(x, y);
    return *(uint32_t*)&h;
}
#define CP16(dst, src) \
    asm volatile("cp.async.cg.shared.global [%0], [%1], 16;" :: "r"(dst), "l"(src))
#define CP_COMMIT() asm volatile("cp.async.commit_group;")
#define CP_WAIT1() asm volatile("cp.async.wait_group 1;")
#define CP_WAIT0() asm volatile("cp.async.wait_group 0;")

// ============================ blocked fp32 router ==========================
#define RT_ 32
#define RXP_ 1033
#define RSMEM_BYTES ((RT_ * RXP_ + RT_ * GE_) * 4)   // 136320

__global__ __launch_bounds__(256) void router_kernel(const float* __restrict__ k_src,
                                                     const float* __restrict__ q_src,
                                                     const float* __restrict__ sel_v,
                                                     const float* __restrict__ sel_o) {
    extern __shared__ float rsm[];
    float* xs = rsm;
    float* sg = rsm + RT_ * RXP_;

    int z = blockIdx.y;
    const float* xsrc = z ? q_src : k_src;
    const float* sel  = z ? sel_o : sel_v;
    float* gout       = z ? g_go  : g_gv;

    int t0 = blockIdx.x * RT_;
    int tid = threadIdx.x;

    for (int i = tid; i < RT_ * (D_ / 4); i += 256) {
        int r = i >> 8, c4 = i & 255;
        float4 v = ((const float4*)(xsrc + (size_t)(t0 + r) * D_))[c4];
        float* dst = xs + r * RXP_ + c4 * 4;
        dst[0] = v.x; dst[1] = v.y; dst[2] = v.z; dst[3] = v.w;
    }
    __syncthreads();

    int g = tid >> 3, slot = tid & 7;
    const float* w = sel + (size_t)g * D_;
    const float* x0 = xs + (slot * 4 + 0) * RXP_;
    const float* x1 = xs + (slot * 4 + 1) * RXP_;
    const float* x2 = xs + (slot * 4 + 2) * RXP_;
    const float* x3 = xs + (slot * 4 + 3) * RXP_;
    float s0 = 0.f, s1 = 0.f, s2 = 0.f, s3 = 0.f;
    #pragma unroll 4
    for (int d = 0; d < D_; d++) {
        float sv = w[d];
        s0 += x0[d] * sv;
        s1 += x1[d] * sv;
        s2 += x2[d] * sv;
        s3 += x3[d] * sv;
    }
    sg[(slot * 4 + 0) * GE_ + g] = s0;
    sg[(slot * 4 + 1) * GE_ + g] = s1;
    sg[(slot * 4 + 2) * GE_ + g] = s2;
    sg[(slot * 4 + 3) * GE_ + g] = s3;
    __syncthreads();

    int t = tid >> 3, h = tid & 7;
    float vals[4];
    #pragma unroll
    for (int e = 0; e < 4; e++)
        vals[e] = 1.f / (1.f + __expf(-sg[t * GE_ + h * 4 + e]));
    int i1 = 0;
    #pragma unroll
    for (int e = 1; e < 4; e++) if (vals[e] > vals[i1]) i1 = e;
    int i2 = -1;
    #pragma unroll
    for (int e = 0; e < 4; e++) {
        if (e == i1) continue;
        if (i2 < 0 || vals[e] > vals[i2]) i2 = e;
    }
    #pragma unroll
    for (int e = 0; e < 4; e++)
        gout[(size_t)(t0 + t) * GE_ + h * 4 + e] = (e == i1 || e == i2) ? vals[e] : 0.f;
}

// ============================ merged convert (fp32 -> fp16) ================
#define CVA_ (TOK_ * D_ / 4)    // 1048576
#define CVW_ (D_ * D_ / 4)      // 262144
#define CVTOT_ (3 * CVA_ + 2 * CVW_)

__global__ void conv_all_kernel(const float* __restrict__ q_src,
                                const float* __restrict__ k_src,
                                const float* __restrict__ v_src,
                                const float* __restrict__ Wq,
                                const float* __restrict__ Wk) {
    int i = blockIdx.x * blockDim.x + threadIdx.x;
    if (i >= CVTOT_) return;
    const float* src;
    __half* dst;
    int j = i;
    if (j < CVA_) { src = q_src; dst = g_qc; }
    else if ((j -= CVA_) < CVA_) { src = k_src; dst = g_kc; }
    else if ((j -= CVA_) < CVA_) { src = v_src; dst = g_vc; }
    else if ((j -= CVA_) < CVW_) { src = Wq; dst = g_wqc; }
    else { j -= CVW_; src = Wk; dst = g_wkc; }
    float4 v = ((const float4*)src)[j];
    ((__half2*)dst)[j * 2 + 0] = __floats2half2_rn(v.x, v.y);
    ((__half2*)dst)[j * 2 + 1] = __floats2half2_rn(v.z, v.w);
}

// ============================ transpose Wv (fp32 -> fp16, (h,dh,e) rows) ===
__global__ void transpose_wv_kernel(const float* __restrict__ src) {
    __shared__ float tile[32][33];
    int z = blockIdx.z;
    int h = z >> 2, e = z & 3;
    const float* s = src + (size_t)z * D_ * DH_;
    int r0 = blockIdx.y * 32, c0 = blockIdx.x * 32;
    int x = threadIdx.x, y = threadIdx.y;
    #pragma unroll
    for (int i = 0; i < 32; i += 8)
        tile[y + i][x] = s[(size_t)(r0 + y + i) * DH_ + c0 + x];
    __syncthreads();
    #pragma unroll
    for (int i = 0; i < 32; i += 8) {
        int dh = c0 + y + i;
        g_wvT[(size_t)(h * 512 + dh * 4 + e) * D_ + r0 + x] = __float2half_rn(tile[x][y + i]);
    }
}

// ============================ transpose (fp32 src -> fp16 dst) =============
__global__ void transpose_kernel(const float* __restrict__ src, __half* __restrict__ dst,
                                 int R, int C) {
    __shared__ float tile[32][33];
    size_t zo = (size_t)blockIdx.z * R * C;
    src += zo; dst += zo;
    int r0 = blockIdx.y * 32, c0 = blockIdx.x * 32;
    int x = threadIdx.x, y = threadIdx.y;
    #pragma unroll
    for (int i = 0; i < 32; i += 8)
        tile[y + i][x] = src[(size_t)(r0 + y + i) * C + c0 + x];
    __syncthreads();
    #pragma unroll
    for (int i = 0; i < 32; i += 8)
        dst[(size_t)(c0 + y + i) * R + r0 + x] = __float2half_rn(tile[x][y + i]);
}

// ============================ fp16 mma GEMM (cp.async + ldmatrix) ==========
// MODE 0: fp32 row-major C.  MODE 1: qk merged, fp16 C [B,H,S,DH].
// MODE 3: vall w/ gate-folding epilogue -> g_v [B,H,S,DH] fp16.
#define PADH_ 36
#define ABUF_ (128 * PADH_)
#define BBUF_ (256 * PADH_)
#define STG_W (ABUF_ + BBUF_)
#define GSMEM_BYTES (3 * STG_W * 4)     // 165888

template<int MODE>
__global__ __launch_bounds__(512) void gemm_f16(const __half* __restrict__ A,
                                                const __half* __restrict__ B,
                                                void* __restrict__ Cv,
                                                int Ktot, int ldc, float alpha,
                                                const __half* __restrict__ A2,
                                                const __half* __restrict__ B2,
                                                void* __restrict__ C2v) {
    extern __shared__ __align__(16) uint32_t dsm[];
    uint32_t sbase = smem_u32(dsm);

    int tid = threadIdx.x;
    int wid = tid >> 5;
    int lane = tid & 31;
    int m0 = blockIdx.y * 128, n0 = blockIdx.x * 256;
    int m0w = (wid >> 2) * 32, n0w = (wid & 3) * 64;

    void* Cp = Cv;
    if (MODE == 1 && blockIdx.z == 1) { A = A2; B = B2; Cp = C2v; }

    int ar0 = tid >> 3, ao0 = (tid & 7) * 8;
    int aS1 = tid + 512;
    int ar1 = aS1 >> 3, ao1 = (aS1 & 7) * 8;
    const __half* Asrc0 = A + (size_t)(m0 + ar0) * Ktot + ao0;
    const __half* Asrc1 = A + (size_t)(m0 + ar1) * Ktot + ao1;
    uint32_t aDst0 = (uint32_t)(ar0 * PADH_ + (ao0 >> 1)) * 4;
    uint32_t aDst1 = (uint32_t)(ar1 * PADH_ + (ao1 >> 1)) * 4;
    const __half* Bsrc[4];
    uint32_t bDst[4];
    #pragma unroll
    for (int j = 0; j < 4; j++) {
        int s = tid + 512 * j;
        int brr = s >> 3, bo = (s & 7) * 8;
        Bsrc[j] = B + (size_t)(n0 + brr) * Ktot + bo;
        bDst[j] = (uint32_t)(ABUF_ + brr * PADH_ + (bo >> 1)) * 4;
    }

    float acc[2][8][4];
    #pragma unroll
    for (int i = 0; i < 2; i++)
        #pragma unroll
        for (int j = 0; j < 8; j++)
            #pragma unroll
            for (int c = 0; c < 4; c++) acc[i][j][c] = 0.f;

    int KT = Ktot >> 6;

    auto copyTile = [&](int kt, int stg) {
        uint32_t so = sbase + (uint32_t)(stg * STG_W * 4);
        int ko = kt * 64;
        CP16(so + aDst0, Asrc0 + ko);
        CP16(so + aDst1, Asrc1 + ko);
        #pragma unroll
        for (int j = 0; j < 4; j++)
            CP16(so + bDst[j], Bsrc[j] + ko);
        CP_COMMIT();
    };

    copyTile(0, 0);
    copyTile(1, 1);

    int g8 = lane >> 3, l8 = lane & 7;
    uint32_t aRow = (uint32_t)(m0w + (g8 & 1) * 8 + l8);
    uint32_t aCo  = (uint32_t)((g8 >> 1) * 4);
    uint32_t bRow = (uint32_t)(n0w + (g8 >> 1) * 8 + l8);
    uint32_t bCo  = (uint32_t)((g8 & 1) * 4);

    for (int kt = 0; kt < KT; kt++) {
        if (kt + 1 < KT) CP_WAIT1(); else CP_WAIT0();
        __syncthreads();

        uint32_t AsAddr = sbase + (uint32_t)((kt % 3) * STG_W * 4);
        uint32_t BsAddr = AsAddr + (uint32_t)(ABUF_ * 4);
        #pragma unroll
        for (int ks = 0; ks < 4; ks++) {
            uint32_t kb = (uint32_t)(ks * 8);
            uint32_t a[2][4], b[8][2];
            #pragma unroll
            for (int mi = 0; mi < 2; mi++)
                ldsm4(AsAddr + ((aRow + mi * 16) * PADH_ + kb + aCo) * 4, a[mi]);
            #pragma unroll
            for (int p = 0; p < 4; p++) {
                uint32_t r4v[4];
                ldsm4(BsAddr + ((bRow + p * 16) * PADH_ + kb + bCo) * 4, r4v);
                b[2 * p][0] = r4v[0]; b[2 * p][1] = r4v[1];
                b[2 * p + 1][0] = r4v[2]; b[2 * p + 1][1] = r4v[3];
            }
            #pragma unroll
            for (int mi = 0; mi < 2; mi++)
                #pragma unroll
                for (int ni = 0; ni < 8; ni++)
                    mma_f16(acc[mi][ni], a[mi], b[ni]);
        }

        if (kt + 2 < KT) copyTile(kt + 2, (kt + 2) % 3);
    }

    int r4 = lane >> 2, c4 = lane & 3;
    #pragma unroll
    for (int mi = 0; mi < 2; mi++) {
        #pragma unroll
        for (int half_m = 0; half_m < 2; half_m++) {
            int m = m0 + m0w + mi * 16 + half_m * 8 + r4;
            int bb = m >> 11, ss = m & (S_ - 1);
            #pragma unroll
            for (int ni = 0; ni < 8; ni++) {
                int n = n0 + n0w + ni * 8 + c4 * 2;
                float ox = acc[mi][ni][half_m * 2 + 0] * alpha;
                float oy = acc[mi][ni][half_m * 2 + 1] * alpha;
                if (MODE == 1) {
                    int h = n >> 7, dh = n & 127;
                    *(__half2*)((__half*)Cp + (((size_t)bb * H_ + h) * S_ + ss) * DH_ + dh) =
                        __floats2half2_rn(ox, oy);
                } else if (MODE == 3) {
                    int h = n >> 9, dh = (n >> 2) & 127, e = n & 3;
                    const float* gp = g_gv + (size_t)m * GE_ + h * 4;
                    float part = ox * gp[e] + oy * gp[e + 1];
                    part += __shfl_xor_sync(0xffffffffu, part, 1);
                    if ((c4 & 1) == 0)
                        *((__half*)Cp + (((size_t)bb * H_ + h) * S_ + ss) * DH_ + dh) =
                            __float2half_rn(part);
                } else {
                    *(float2*)((float*)Cp + (size_t)m * ldc + n) = make_float2(ox, oy);
                }
            }
        }
    }
}

// ============================ fp16 flash attention (ldmatrix + trans V) ====
// K and V both [kv][dh] fp16 from g_k/g_v; V fragments via ldmatrix.trans.
// Epilogue writes gated expansion to g_aexp directly.
#define APH_ 68
#define ATILE_ (128 * APH_)
#define QS_OFF 0
#define KS_OFF ATILE_
#define VT_OFF (3 * ATILE_)
#define PS_OFF (5 * ATILE_)
#define ATTN_SMEM (6 * ATILE_ * 4)      // 208896

__global__ __launch_bounds__(256) void attn_tc_kernel() {
    extern __shared__ __align__(16) uint32_t asm_[];
    uint32_t sbase = smem_u32(asm_);
    uint32_t* Qs = asm_ + QS_OFF;
    uint32_t* Ps = asm_ + PS_OFF;
    uint32_t QsAddr = sbase;
    uint32_t PsAddr = sbase + (uint32_t)(PS_OFF * 4);

    int bh = blockIdx.y;
    int q0 = blockIdx.x * 128;
    const __half* Qg = g_q + (size_t)bh * S_ * DH_;
    const __half* Kg = g_k + (size_t)bh * S_ * DH_;
    const __half* Vg = g_v + (size_t)bh * S_ * DH_;

    int tid = threadIdx.x;
    int wid = tid >> 5;
    int lane = tid & 31;
    int r4 = lane >> 2, c4 = lane & 3;
    int m0w = wid * 16;
    int g8 = lane >> 3, l8 = lane & 7;
    uint32_t aRow = (uint32_t)(m0w + (g8 & 1) * 8 + l8);
    uint32_t aCo  = (uint32_t)((g8 >> 1) * 4);
    uint32_t bRow = (uint32_t)((g8 >> 1) * 8 + l8);
    uint32_t bCo  = (uint32_t)((g8 & 1) * 4);
    // trans-V per-thread offsets: row = ks*16 + (g8&1)*8 + l8, colw = p*8 + (g8>>1)*4
    uint32_t vRow = (uint32_t)((g8 & 1) * 8 + l8);
    uint32_t vCo  = (uint32_t)((g8 >> 1) * 4);

    for (int i = tid; i < 2048; i += 256) {
        int r = i >> 4, w = i & 15;
        *(uint4*)&Qs[r * APH_ + w * 4] = *(const uint4*)(Qg + (size_t)(q0 + r) * DH_ + w * 8);
    }

    auto copyKV = [&](int j0, int buf) {
        uint32_t ks = sbase + (uint32_t)((KS_OFF + buf * ATILE_) * 4);
        uint32_t vs = sbase + (uint32_t)((VT_OFF + buf * ATILE_) * 4);
        #pragma unroll
        for (int jj = 0; jj < 8; jj++) {
            int i = tid + 256 * jj;
            int r = i >> 4, w = i & 15;
            CP16(ks + (uint32_t)(r * APH_ + w * 4) * 4, Kg + (size_t)(j0 + r) * DH_ + w * 8);
            CP16(vs + (uint32_t)(r * APH_ + w * 4) * 4, Vg + (size_t)(j0 + r) * DH_ + w * 8);
        }
        CP_COMMIT();
    };

    copyKV(0, 0);

    float o[16][4];
    #pragma unroll
    for (int ni = 0; ni < 16; ni++)
        #pragma unroll
        for (int c = 0; c < 4; c++) o[ni][c] = 0.f;
    float mA = -1e30f, mB = -1e30f, lA = 0.f, lB = 0.f;

    for (int it = 0; it < S_ / 128; it++) {
        int buf = it & 1;
        __syncthreads();
        if (it + 1 < S_ / 128) {
            copyKV((it + 1) * 128, buf ^ 1);
            CP_WAIT1();
        } else {
            CP_WAIT0();
        }
        __syncthreads();

        uint32_t KsAddr = sbase + (uint32_t)((KS_OFF + buf * ATILE_) * 4);
        uint32_t VtAddr = sbase + (uint32_t)((VT_OFF + buf * ATILE_) * 4);

        float sf[16][4];
        #pragma unroll
        for (int ni = 0; ni < 16; ni++)
            #pragma unroll
            for (int c = 0; c < 4; c++) sf[ni][c] = 0.f;

        #pragma unroll
        for (int ks = 0; ks < 8; ks++) {
            uint32_t kb = (uint32_t)(ks * 8);
            uint32_t a[4], b[16][2];
            ldsm4(QsAddr + (aRow * APH_ + kb + aCo) * 4, a);
            #pragma unroll
            for (int p = 0; p < 8; p++) {
                uint32_t r4v[4];
                ldsm4(KsAddr + ((bRow + p * 16) * APH_ + kb + bCo) * 4, r4v);
                b[2 * p][0] = r4v[0]; b[2 * p][1] = r4v[1];
                b[2 * p + 1][0] = r4v[2]; b[2 * p + 1][1] = r4v[3];
            }
            #pragma unroll
            for (int ni = 0; ni < 16; ni++)
                mma_f16(sf[ni], a, b[ni]);
        }

        float mxA = -1e30f, mxB = -1e30f;
        #pragma unroll
        for (int ni = 0; ni < 16; ni++) {
            mxA = fmaxf(mxA, fmaxf(sf[ni][0], sf[ni][1]));
            mxB = fmaxf(mxB, fmaxf(sf[ni][2], sf[ni][3]));
        }
        mxA = fmaxf(mxA, __shfl_xor_sync(0xffffffffu, mxA, 1));
        mxA = fmaxf(mxA, __shfl_xor_sync(0xffffffffu, mxA, 2));
        mxB = fmaxf(mxB, __shfl_xor_sync(0xffffffffu, mxB, 1));
        mxB = fmaxf(mxB, __shfl_xor_sync(0xffffffffu, mxB, 2));
        float mnA = fmaxf(mA, mxA), mnB = fmaxf(mB, mxB);
        float scA = __expf(mA - mnA), scB = __expf(mB - mnB);
        float sA = 0.f, sB = 0.f;
        int prA = (m0w + r4) * APH_;
        int prB = prA + 8 * APH_;
        #pragma unroll
        for (int ni = 0; ni < 16; ni++) {
            float e0 = __expf(sf[ni][0] - mnA);
            float e1 = __expf(sf[ni][1] - mnA);
            float e2 = __expf(sf[ni][2] - mnB);
            float e3 = __expf(sf[ni][3] - mnB);
            sA += e0 + e1; sB += e2 + e3;
            int cw = ni * 4 + c4;
            Ps[prA + cw] = pack_h2(e0, e1);
            Ps[prB + cw] = pack_h2(e2, e3);
        }
        sA += __shfl_xor_sync(0xffffffffu, sA, 1);
        sA += __shfl_xor_sync(0xffffffffu, sA, 2);
        sB += __shfl_xor_sync(0xffffffffu, sB, 1);
        sB += __shfl_xor_sync(0xffffffffu, sB, 2);
        lA = lA * scA + sA; lB = lB * scB + sB;
        mA = mnA; mB = mnB;
        #pragma unroll
        for (int ni = 0; ni < 16; ni++) {
            o[ni][0] *= scA; o[ni][1] *= scA;
            o[ni][2] *= scB; o[ni][3] *= scB;
        }
        __syncwarp();

        // O += P V : V fragments via ldmatrix.trans from [kv][dh] layout
        #pragma unroll
        for (int ks = 0; ks < 8; ks++) {
            uint32_t kb = (uint32_t)(ks * 8);
            uint32_t a[4], b[16][2];
            ldsm4(PsAddr + (aRow * APH_ + kb + aCo) * 4, a);
            #pragma unroll
            for (int p = 0; p < 8; p++) {
                uint32_t r4v[4];
                ldsm4t(VtAddr + ((ks * 16 + vRow) * APH_ + p * 8 + vCo) * 4, r4v);
                b[2 * p][0] = r4v[0]; b[2 * p][1] = r4v[1];
                b[2 * p + 1][0] = r4v[2]; b[2 * p + 1][1] = r4v[3];
            }
            #pragma unroll
            for (int ni = 0; ni < 16; ni++)
                mma_f16(o[ni], a, b[ni]);
        }
    }

    // epilogue: write gated expansion directly (kills res + expand)
    float invA = 1.f / lA, invB = 1.f / lB;
    int bb = bh >> 3, h = bh & 7;
    int sApos = q0 + m0w + r4;
    int tA = bb * S_ + sApos;
    int tB = tA + 8;
    const float* gpA = g_go + (size_t)tA * GE_ + h * 4;
    const float* gpB = g_go + (size_t)tB * GE_ + h * 4;
    float gA[4], gB[4];
    #pragma unroll
    for (int e = 0; e < 4; e++) { gA[e] = gpA[e]; gB[e] = gpB[e]; }
    __half* baseA = g_aexp + (size_t)tA * KEXP_ + h * 512;
    __half* baseB = g_aexp + (size_t)tB * KEXP_ + h * 512;
    #pragma unroll
    for (int ni = 0; ni < 16; ni++) {
        int cc = ni * 8 + c4 * 2;
        float ax = o[ni][0] * invA, ay = o[ni][1] * invA;
        float bx = o[ni][2] * invB, by = o[ni][3] * invB;
        #pragma unroll
        for (int e = 0; e < 4; e++) {
            *(__half2*)(baseA + e * 128 + cc) = __floats2half2_rn(ax * gA[e], ay * gA[e]);
            *(__half2*)(baseB + e * 128 + cc) = __floats2half2_rn(bx * gB[e], by * gB[e]);
        }
    }
}

// ---------------------------------------------------------------------------
extern "C" void kernel_launch(void* const* d_in, const int* in_sizes, int n_in,
                              void* d_out, int out_size) {
    const float* q_src = (const float*)d_in[0];
    const float* k_src = (const float*)d_in[1];
    const float* v_src = (const float*)d_in[2];
    const float* Wq    = (const float*)d_in[3];
    const float* Wk    = (const float*)d_in[4];
    const float* Wv    = (const float*)d_in[5];
    const float* Wo    = (const float*)d_in[6];
    const float* sel_v = (const float*)d_in[7];
    const float* sel_o = (const float*)d_in[8];
    float* outp = (float*)d_out;

    cudaFuncSetAttribute(attn_tc_kernel, cudaFuncAttributeMaxDynamicSharedMemorySize, ATTN_SMEM);
    cudaFuncSetAttribute(gemm_f16<0>, cudaFuncAttributeMaxDynamicSharedMemorySize, GSMEM_BYTES);
    cudaFuncSetAttribute(gemm_f16<1>, cudaFuncAttributeMaxDynamicSharedMemorySize, GSMEM_BYTES);
    cudaFuncSetAttribute(gemm_f16<3>, cudaFuncAttributeMaxDynamicSharedMemorySize, GSMEM_BYTES);
    cudaFuncSetAttribute(router_kernel, cudaFuncAttributeMaxDynamicSharedMemorySize, RSMEM_BYTES);

    __half *gq, *gk, *gv, *gaexp, *gwvT, *gwoT, *gqc, *gkc, *gvc, *gwqc, *gwkc;
    cudaGetSymbolAddress((void**)&gq, g_q);
    cudaGetSymbolAddress((void**)&gk, g_k);
    cudaGetSymbolAddress((void**)&gv, g_v);
    cudaGetSymbolAddress((void**)&gaexp, g_aexp);
    cudaGetSymbolAddress((void**)&gwvT, g_wvT);
    cudaGetSymbolAddress((void**)&gwoT, g_woT);
    cudaGetSymbolAddress((void**)&gqc, g_qc);
    cudaGetSymbolAddress((void**)&gkc, g_kc);
    cudaGetSymbolAddress((void**)&gvc, g_vc);
    cudaGetSymbolAddress((void**)&gwqc, g_wqc);
    cudaGetSymbolAddress((void**)&gwkc, g_wkc);

    const float scale = 0.29730177875068026f;  // 128^-0.25

    router_kernel<<<dim3(TOK_ / RT_, 2), 256, RSMEM_BYTES>>>(k_src, q_src, sel_v, sel_o);

    conv_all_kernel<<<(CVTOT_ + 255) / 256, 256>>>(q_src, k_src, v_src, Wq, Wk);

    transpose_wv_kernel<<<dim3(DH_ / 32, D_ / 32, GE_), dim3(32, 8)>>>(Wv);
    transpose_kernel<<<dim3(D_ / 32, KEXP_ / 32, 1), dim3(32, 8)>>>(Wo, gwoT, KEXP_, D_);

    // merged q/k projections: M=4096, N=1024, K=1024; z=0 -> q, z=1 -> k
    gemm_f16<1><<<dim3(D_ / 256, TOK_ / 128, 2), 512, GSMEM_BYTES>>>(
        gqc, gwqc, gq, D_, 0, scale, gkc, gwkc, gk);

    // gated V: M=4096, N=4096 (h,dh,e), K=1024 -> g_v fp16 directly
    gemm_f16<3><<<dim3(KEXP_ / 256, TOK_ / 128), 512, GSMEM_BYTES>>>(
        gvc, gwvT, gv, D_, 0, 1.0f, nullptr, nullptr, nullptr);

    attn_tc_kernel<<<dim3(S_ / 128, B_ * H_), 256, ATTN_SMEM>>>();

    // out: M=4096, N=1024, K=4096 -> fp32
    gemm_f16<0><<<dim3(D_ / 256, TOK_ / 128), 512, GSMEM_BYTES>>>(
        gaexp, gwoT, outp, KEXP_, D_, 1.0f, nullptr, nullptr, nullptr);
}

// round 17
// speedup vs baseline: 1.0442x; 1.0308x over previous
#include <cuda_runtime.h>
#include <cuda_fp16.h>
#include <math.h>
#include <stdint.h>

// ---------------------------------------------------------------------------
// SwitchHeadCore: B=2,S=2048,D=1024,H=8,E=4,K=2,DH=128
// fp16 m16n8k16 + ldmatrix(+trans) + cp.async.  Fused qk+vall GEMM launch,
// gate-folding vall epilogue, gated-expansion attention epilogue,
// fp32 blocked router.
// ---------------------------------------------------------------------------

#define B_ 2
#define S_ 2048
#define D_ 1024
#define H_ 8
#define E_ 4
#define DH_ 128
#define TOK_ (B_ * S_)              // 4096
#define GE_ (H_ * E_)               // 32
#define KEXP_ 4096                  // H*E*DH

__device__ __align__(16) __half g_q[TOK_ * D_];     // [B,H,S,DH]
__device__ __align__(16) __half g_k[TOK_ * D_];
__device__ __align__(16) __half g_v[TOK_ * D_];     // [B,H,S,DH]
__device__ float g_gv[TOK_ * GE_];
__device__ float g_go[TOK_ * GE_];
__device__ __align__(16) __half g_aexp[(size_t)TOK_ * KEXP_];
__device__ __align__(16) __half g_wvT[(size_t)KEXP_ * D_];    // [(h,dh,e), d]
__device__ __align__(16) __half g_woT[(size_t)D_ * KEXP_];    // [o, (h,e,dh)]
__device__ __align__(16) __half g_qc[TOK_ * D_];
__device__ __align__(16) __half g_kc[TOK_ * D_];
__device__ __align__(16) __half g_vc[TOK_ * D_];
__device__ __align__(16) __half g_wqc[D_ * D_];
__device__ __align__(16) __half g_wkc[D_ * D_];

// ============================ helpers ======================================
__device__ __forceinline__ void mma_f16(float* d, const uint32_t* a, const uint32_t* b) {
    asm volatile(
        "mma.sync.aligned.m16n8k16.row.col.f32.f16.f16.f32 "
        "{%0,%1,%2,%3}, {%4,%5,%6,%7}, {%8,%9}, {%0,%1,%2,%3};\n"
        : "+f"(d[0]), "+f"(d[1]), "+f"(d[2]), "+f"(d[3])
        : "r"(a[0]), "r"(a[1]), "r"(a[2]), "r"(a[3]), "r"(b[0]), "r"(b[1]));
}
__device__ __forceinline__ void ldsm4(uint32_t addr, uint32_t* r) {
    asm volatile("ldmatrix.sync.aligned.m8n8.x4.shared.b16 {%0,%1,%2,%3}, [%4];"
        : "=r"(r[0]), "=r"(r[1]), "=r"(r[2]), "=r"(r[3]) : "r"(addr));
}
__device__ __forceinline__ void ldsm4t(uint32_t addr, uint32_t* r) {
    asm volatile("ldmatrix.sync.aligned.m8n8.x4.trans.shared.b16 {%0,%1,%2,%3}, [%4];"
        : "=r"(r[0]), "=r"(r[1]), "=r"(r[2]), "=r"(r[3]) : "r"(addr));
}
__device__ __forceinline__ uint32_t smem_u32(const void* p) {
    uint32_t a;
    asm("{ .reg .u64 t; cvta.to.shared.u64 t, %1; cvt.u32.u64 %0, t; }" : "=r"(a) : "l"(p));
    return a;
}
__device__ __forceinline__ uint32_t pack_h2(float x, float y) {
    __half2 h = __floats2half2_rn(x, y);
    return *(uint32_t*)&h;
}
#define CP16(dst, src) \
    asm volatile("cp.async.cg.shared.global [%0], [%1], 16;" :: "r"(dst), "l"(src))
#define CP_COMMIT() asm volatile("cp.async.commit_group;")
#define CP_WAIT1() asm volatile("cp.async.wait_group 1;")
#define CP_WAIT0() asm volatile("cp.async.wait_group 0;")

// ============================ blocked fp32 router ==========================
#define RT_ 32
#define RXP_ 1033
#define RSMEM_BYTES ((RT_ * RXP_ + RT_ * GE_) * 4)   // 136320

__global__ __launch_bounds__(256) void router_kernel(const float* __restrict__ k_src,
                                                     const float* __restrict__ q_src,
                                                     const float* __restrict__ sel_v,
                                                     const float* __restrict__ sel_o) {
    extern __shared__ float rsm[];
    float* xs = rsm;
    float* sg = rsm + RT_ * RXP_;

    int z = blockIdx.y;
    const float* xsrc = z ? q_src : k_src;
    const float* sel  = z ? sel_o : sel_v;
    float* gout       = z ? g_go  : g_gv;

    int t0 = blockIdx.x * RT_;
    int tid = threadIdx.x;

    for (int i = tid; i < RT_ * (D_ / 4); i += 256) {
        int r = i >> 8, c4 = i & 255;
        float4 v = ((const float4*)(xsrc + (size_t)(t0 + r) * D_))[c4];
        float* dst = xs + r * RXP_ + c4 * 4;
        dst[0] = v.x; dst[1] = v.y; dst[2] = v.z; dst[3] = v.w;
    }
    __syncthreads();

    int g = tid >> 3, slot = tid & 7;
    const float* w = sel + (size_t)g * D_;
    const float* x0 = xs + (slot * 4 + 0) * RXP_;
    const float* x1 = xs + (slot * 4 + 1) * RXP_;
    const float* x2 = xs + (slot * 4 + 2) * RXP_;
    const float* x3 = xs + (slot * 4 + 3) * RXP_;
    float s0 = 0.f, s1 = 0.f, s2 = 0.f, s3 = 0.f;
    #pragma unroll 4
    for (int d = 0; d < D_; d++) {
        float sv = w[d];
        s0 += x0[d] * sv;
        s1 += x1[d] * sv;
        s2 += x2[d] * sv;
        s3 += x3[d] * sv;
    }
    sg[(slot * 4 + 0) * GE_ + g] = s0;
    sg[(slot * 4 + 1) * GE_ + g] = s1;
    sg[(slot * 4 + 2) * GE_ + g] = s2;
    sg[(slot * 4 + 3) * GE_ + g] = s3;
    __syncthreads();

    int t = tid >> 3, h = tid & 7;
    float vals[4];
    #pragma unroll
    for (int e = 0; e < 4; e++)
        vals[e] = 1.f / (1.f + __expf(-sg[t * GE_ + h * 4 + e]));
    int i1 = 0;
    #pragma unroll
    for (int e = 1; e < 4; e++) if (vals[e] > vals[i1]) i1 = e;
    int i2 = -1;
    #pragma unroll
    for (int e = 0; e < 4; e++) {
        if (e == i1) continue;
        if (i2 < 0 || vals[e] > vals[i2]) i2 = e;
    }
    #pragma unroll
    for (int e = 0; e < 4; e++)
        gout[(size_t)(t0 + t) * GE_ + h * 4 + e] = (e == i1 || e == i2) ? vals[e] : 0.f;
}

// ============================ merged convert (fp32 -> fp16) ================
#define CVA_ (TOK_ * D_ / 4)    // 1048576
#define CVW_ (D_ * D_ / 4)      // 262144
#define CVTOT_ (3 * CVA_ + 2 * CVW_)

__global__ void conv_all_kernel(const float* __restrict__ q_src,
                                const float* __restrict__ k_src,
                                const float* __restrict__ v_src,
                                const float* __restrict__ Wq,
                                const float* __restrict__ Wk) {
    int i = blockIdx.x * blockDim.x + threadIdx.x;
    if (i >= CVTOT_) return;
    const float* src;
    __half* dst;
    int j = i;
    if (j < CVA_) { src = q_src; dst = g_qc; }
    else if ((j -= CVA_) < CVA_) { src = k_src; dst = g_kc; }
    else if ((j -= CVA_) < CVA_) { src = v_src; dst = g_vc; }
    else if ((j -= CVA_) < CVW_) { src = Wq; dst = g_wqc; }
    else { j -= CVW_; src = Wk; dst = g_wkc; }
    float4 v = ((const float4*)src)[j];
    ((__half2*)dst)[j * 2 + 0] = __floats2half2_rn(v.x, v.y);
    ((__half2*)dst)[j * 2 + 1] = __floats2half2_rn(v.z, v.w);
}

// ============================ transpose Wv (fp32 -> fp16, (h,dh,e) rows) ===
__global__ void transpose_wv_kernel(const float* __restrict__ src) {
    __shared__ float tile[32][33];
    int z = blockIdx.z;
    int h = z >> 2, e = z & 3;
    const float* s = src + (size_t)z * D_ * DH_;
    int r0 = blockIdx.y * 32, c0 = blockIdx.x * 32;
    int x = threadIdx.x, y = threadIdx.y;
    #pragma unroll
    for (int i = 0; i < 32; i += 8)
        tile[y + i][x] = s[(size_t)(r0 + y + i) * DH_ + c0 + x];
    __syncthreads();
    #pragma unroll
    for (int i = 0; i < 32; i += 8) {
        int dh = c0 + y + i;
        g_wvT[(size_t)(h * 512 + dh * 4 + e) * D_ + r0 + x] = __float2half_rn(tile[x][y + i]);
    }
}

// ============================ transpose (fp32 src -> fp16 dst) =============
__global__ void transpose_kernel(const float* __restrict__ src, __half* __restrict__ dst,
                                 int R, int C) {
    __shared__ float tile[32][33];
    size_t zo = (size_t)blockIdx.z * R * C;
    src += zo; dst += zo;
    int r0 = blockIdx.y * 32, c0 = blockIdx.x * 32;
    int x = threadIdx.x, y = threadIdx.y;
    #pragma unroll
    for (int i = 0; i < 32; i += 8)
        tile[y + i][x] = src[(size_t)(r0 + y + i) * C + c0 + x];
    __syncthreads();
    #pragma unroll
    for (int i = 0; i < 32; i += 8)
        dst[(size_t)(c0 + y + i) * R + r0 + x] = __float2half_rn(tile[x][y + i]);
}

// ============================ fused qk+vall GEMM (K=1024) ==================
// grid.x: [0,4) q-proj, [4,8) k-proj, [8,24) vall.  All: M=4096, BK=64,
// block 128x256, 512 thr, 3-stage cp.async + ldmatrix.
// q/k epilogue: fp16 [B,H,S,DH] * scale.  vall: gate-folding -> g_v.
#define PADH_ 36
#define ABUF_ (128 * PADH_)
#define BBUF_ (256 * PADH_)
#define STG_W (ABUF_ + BBUF_)
#define GSMEM_BYTES (3 * STG_W * 4)     // 165888

__global__ __launch_bounds__(512) void gemm_qkv(float scale) {
    extern __shared__ __align__(16) uint32_t dsm[];
    uint32_t sbase = smem_u32(dsm);

    int tid = threadIdx.x;
    int wid = tid >> 5;
    int lane = tid & 31;
    int bx = blockIdx.x;
    int seg = (bx < 4) ? 0 : (bx < 8) ? 1 : 2;
    int nx = (seg == 0) ? bx : (seg == 1) ? bx - 4 : bx - 8;
    const __half* A = (seg == 0) ? g_qc : (seg == 1) ? g_kc : g_vc;
    const __half* B = (seg == 0) ? g_wqc : (seg == 1) ? g_wkc : g_wvT;
    __half* Cp = (seg == 0) ? g_q : (seg == 1) ? g_k : g_v;
    float alpha = (seg == 2) ? 1.0f : scale;

    int m0 = blockIdx.y * 128, n0 = nx * 256;
    int m0w = (wid >> 2) * 32, n0w = (wid & 3) * 64;
    const int Ktot = D_;

    int ar0 = tid >> 3, ao0 = (tid & 7) * 8;
    int aS1 = tid + 512;
    int ar1 = aS1 >> 3, ao1 = (aS1 & 7) * 8;
    const __half* Asrc0 = A + (size_t)(m0 + ar0) * Ktot + ao0;
    const __half* Asrc1 = A + (size_t)(m0 + ar1) * Ktot + ao1;
    uint32_t aDst0 = (uint32_t)(ar0 * PADH_ + (ao0 >> 1)) * 4;
    uint32_t aDst1 = (uint32_t)(ar1 * PADH_ + (ao1 >> 1)) * 4;
    const __half* Bsrc[4];
    uint32_t bDst[4];
    #pragma unroll
    for (int j = 0; j < 4; j++) {
        int s = tid + 512 * j;
        int brr = s >> 3, bo = (s & 7) * 8;
        Bsrc[j] = B + (size_t)(n0 + brr) * Ktot + bo;
        bDst[j] = (uint32_t)(ABUF_ + brr * PADH_ + (bo >> 1)) * 4;
    }

    float acc[2][8][4];
    #pragma unroll
    for (int i = 0; i < 2; i++)
        #pragma unroll
        for (int j = 0; j < 8; j++)
            #pragma unroll
            for (int c = 0; c < 4; c++) acc[i][j][c] = 0.f;

    const int KT = Ktot >> 6;

    auto copyTile = [&](int kt, int stg) {
        uint32_t so = sbase + (uint32_t)(stg * STG_W * 4);
        int ko = kt * 64;
        CP16(so + aDst0, Asrc0 + ko);
        CP16(so + aDst1, Asrc1 + ko);
        #pragma unroll
        for (int j = 0; j < 4; j++)
            CP16(so + bDst[j], Bsrc[j] + ko);
        CP_COMMIT();
    };

    copyTile(0, 0);
    copyTile(1, 1);

    int g8 = lane >> 3, l8 = lane & 7;
    uint32_t aRow = (uint32_t)(m0w + (g8 & 1) * 8 + l8);
    uint32_t aCo  = (uint32_t)((g8 >> 1) * 4);
    uint32_t bRow = (uint32_t)(n0w + (g8 >> 1) * 8 + l8);
    uint32_t bCo  = (uint32_t)((g8 & 1) * 4);

    for (int kt = 0; kt < KT; kt++) {
        if (kt + 1 < KT) CP_WAIT1(); else CP_WAIT0();
        __syncthreads();

        uint32_t AsAddr = sbase + (uint32_t)((kt % 3) * STG_W * 4);
        uint32_t BsAddr = AsAddr + (uint32_t)(ABUF_ * 4);
        #pragma unroll
        for (int ks = 0; ks < 4; ks++) {
            uint32_t kb = (uint32_t)(ks * 8);
            uint32_t a[2][4], b[8][2];
            #pragma unroll
            for (int mi = 0; mi < 2; mi++)
                ldsm4(AsAddr + ((aRow + mi * 16) * PADH_ + kb + aCo) * 4, a[mi]);
            #pragma unroll
            for (int p = 0; p < 4; p++) {
                uint32_t r4v[4];
                ldsm4(BsAddr + ((bRow + p * 16) * PADH_ + kb + bCo) * 4, r4v);
                b[2 * p][0] = r4v[0]; b[2 * p][1] = r4v[1];
                b[2 * p + 1][0] = r4v[2]; b[2 * p + 1][1] = r4v[3];
            }
            #pragma unroll
            for (int mi = 0; mi < 2; mi++)
                #pragma unroll
                for (int ni = 0; ni < 8; ni++)
                    mma_f16(acc[mi][ni], a[mi], b[ni]);
        }

        if (kt + 2 < KT) copyTile(kt + 2, (kt + 2) % 3);
    }

    int r4 = lane >> 2, c4 = lane & 3;
    #pragma unroll
    for (int mi = 0; mi < 2; mi++) {
        #pragma unroll
        for (int half_m = 0; half_m < 2; half_m++) {
            int m = m0 + m0w + mi * 16 + half_m * 8 + r4;
            int bb = m >> 11, ss = m & (S_ - 1);
            #pragma unroll
            for (int ni = 0; ni < 8; ni++) {
                int n = n0 + n0w + ni * 8 + c4 * 2;
                float ox = acc[mi][ni][half_m * 2 + 0] * alpha;
                float oy = acc[mi][ni][half_m * 2 + 1] * alpha;
                if (seg != 2) {
                    int h = n >> 7, dh = n & 127;
                    *(__half2*)(Cp + (((size_t)bb * H_ + h) * S_ + ss) * DH_ + dh) =
                        __floats2half2_rn(ox, oy);
                } else {
                    int h = n >> 9, dh = (n >> 2) & 127, e = n & 3;
                    const float* gp = g_gv + (size_t)m * GE_ + h * 4;
                    float part = ox * gp[e] + oy * gp[e + 1];
                    part += __shfl_xor_sync(0xffffffffu, part, 1);
                    if ((c4 & 1) == 0)
                        *(Cp + (((size_t)bb * H_ + h) * S_ + ss) * DH_ + dh) =
                            __float2half_rn(part);
                }
            }
        }
    }
}

// ============================ out GEMM (K=4096, fp32 out) ==================
__global__ __launch_bounds__(512) void gemm_out(float* __restrict__ C) {
    extern __shared__ __align__(16) uint32_t dsm[];
    uint32_t sbase = smem_u32(dsm);

    int tid = threadIdx.x;
    int wid = tid >> 5;
    int lane = tid & 31;
    int m0 = blockIdx.y * 128, n0 = blockIdx.x * 256;
    int m0w = (wid >> 2) * 32, n0w = (wid & 3) * 64;
    const int Ktot = KEXP_;
    const __half* A = g_aexp;
    const __half* B = g_woT;

    int ar0 = tid >> 3, ao0 = (tid & 7) * 8;
    int aS1 = tid + 512;
    int ar1 = aS1 >> 3, ao1 = (aS1 & 7) * 8;
    const __half* Asrc0 = A + (size_t)(m0 + ar0) * Ktot + ao0;
    const __half* Asrc1 = A + (size_t)(m0 + ar1) * Ktot + ao1;
    uint32_t aDst0 = (uint32_t)(ar0 * PADH_ + (ao0 >> 1)) * 4;
    uint32_t aDst1 = (uint32_t)(ar1 * PADH_ + (ao1 >> 1)) * 4;
    const __half* Bsrc[4];
    uint32_t bDst[4];
    #pragma unroll
    for (int j = 0; j < 4; j++) {
        int s = tid + 512 * j;
        int brr = s >> 3, bo = (s & 7) * 8;
        Bsrc[j] = B + (size_t)(n0 + brr) * Ktot + bo;
        bDst[j] = (uint32_t)(ABUF_ + brr * PADH_ + (bo >> 1)) * 4;
    }

    float acc[2][8][4];
    #pragma unroll
    for (int i = 0; i < 2; i++)
        #pragma unroll
        for (int j = 0; j < 8; j++)
            #pragma unroll
            for (int c = 0; c < 4; c++) acc[i][j][c] = 0.f;

    const int KT = Ktot >> 6;

    auto copyTile = [&](int kt, int stg) {
        uint32_t so = sbase + (uint32_t)(stg * STG_W * 4);
        int ko = kt * 64;
        CP16(so + aDst0, Asrc0 + ko);
        CP16(so + aDst1, Asrc1 + ko);
        #pragma unroll
        for (int j = 0; j < 4; j++)
            CP16(so + bDst[j], Bsrc[j] + ko);
        CP_COMMIT();
    };

    copyTile(0, 0);
    copyTile(1, 1);

    int g8 = lane >> 3, l8 = lane & 7;
    uint32_t aRow = (uint32_t)(m0w + (g8 & 1) * 8 + l8);
    uint32_t aCo  = (uint32_t)((g8 >> 1) * 4);
    uint32_t bRow = (uint32_t)(n0w + (g8 >> 1) * 8 + l8);
    uint32_t bCo  = (uint32_t)((g8 & 1) * 4);

    for (int kt = 0; kt < KT; kt++) {
        if (kt + 1 < KT) CP_WAIT1(); else CP_WAIT0();
        __syncthreads();

        uint32_t AsAddr = sbase + (uint32_t)((kt % 3) * STG_W * 4);
        uint32_t BsAddr = AsAddr + (uint32_t)(ABUF_ * 4);
        #pragma unroll
        for (int ks = 0; ks < 4; ks++) {
            uint32_t kb = (uint32_t)(ks * 8);
            uint32_t a[2][4], b[8][2];
            #pragma unroll
            for (int mi = 0; mi < 2; mi++)
                ldsm4(AsAddr + ((aRow + mi * 16) * PADH_ + kb + aCo) * 4, a[mi]);
            #pragma unroll
            for (int p = 0; p < 4; p++) {
                uint32_t r4v[4];
                ldsm4(BsAddr + ((bRow + p * 16) * PADH_ + kb + bCo) * 4, r4v);
                b[2 * p][0] = r4v[0]; b[2 * p][1] = r4v[1];
                b[2 * p + 1][0] = r4v[2]; b[2 * p + 1][1] = r4v[3];
            }
            #pragma unroll
            for (int mi = 0; mi < 2; mi++)
                #pragma unroll
                for (int ni = 0; ni < 8; ni++)
                    mma_f16(acc[mi][ni], a[mi], b[ni]);
        }

        if (kt + 2 < KT) copyTile(kt + 2, (kt + 2) % 3);
    }

    int r4 = lane >> 2, c4 = lane & 3;
    #pragma unroll
    for (int mi = 0; mi < 2; mi++) {
        #pragma unroll
        for (int half_m = 0; half_m < 2; half_m++) {
            int m = m0 + m0w + mi * 16 + half_m * 8 + r4;
            #pragma unroll
            for (int ni = 0; ni < 8; ni++) {
                int n = n0 + n0w + ni * 8 + c4 * 2;
                *(float2*)(C + (size_t)m * D_ + n) =
                    make_float2(acc[mi][ni][half_m * 2 + 0], acc[mi][ni][half_m * 2 + 1]);
            }
        }
    }
}

// ============================ fp16 flash attention (ldmatrix + trans V) ====
#define APH_ 68
#define ATILE_ (128 * APH_)
#define QS_OFF 0
#define KS_OFF ATILE_
#define VT_OFF (3 * ATILE_)
#define PS_OFF (5 * ATILE_)
#define ATTN_SMEM (6 * ATILE_ * 4)      // 208896

__global__ __launch_bounds__(256) void attn_tc_kernel() {
    extern __shared__ __align__(16) uint32_t asm_[];
    uint32_t sbase = smem_u32(asm_);
    uint32_t* Qs = asm_ + QS_OFF;
    uint32_t* Ps = asm_ + PS_OFF;
    uint32_t QsAddr = sbase;
    uint32_t PsAddr = sbase + (uint32_t)(PS_OFF * 4);

    int bh = blockIdx.y;
    int q0 = blockIdx.x * 128;
    const __half* Qg = g_q + (size_t)bh * S_ * DH_;
    const __half* Kg = g_k + (size_t)bh * S_ * DH_;
    const __half* Vg = g_v + (size_t)bh * S_ * DH_;

    int tid = threadIdx.x;
    int wid = tid >> 5;
    int lane = tid & 31;
    int r4 = lane >> 2, c4 = lane & 3;
    int m0w = wid * 16;
    int g8 = lane >> 3, l8 = lane & 7;
    uint32_t aRow = (uint32_t)(m0w + (g8 & 1) * 8 + l8);
    uint32_t aCo  = (uint32_t)((g8 >> 1) * 4);
    uint32_t bRow = (uint32_t)((g8 >> 1) * 8 + l8);
    uint32_t bCo  = (uint32_t)((g8 & 1) * 4);
    uint32_t vRow = (uint32_t)((g8 & 1) * 8 + l8);
    uint32_t vCo  = (uint32_t)((g8 >> 1) * 4);

    for (int i = tid; i < 2048; i += 256) {
        int r = i >> 4, w = i & 15;
        *(uint4*)&Qs[r * APH_ + w * 4] = *(const uint4*)(Qg + (size_t)(q0 + r) * DH_ + w * 8);
    }

    auto copyKV = [&](int j0, int buf) {
        uint32_t ks = sbase + (uint32_t)((KS_OFF + buf * ATILE_) * 4);
        uint32_t vs = sbase + (uint32_t)((VT_OFF + buf * ATILE_) * 4);
        #pragma unroll
        for (int jj = 0; jj < 8; jj++) {
            int i = tid + 256 * jj;
            int r = i >> 4, w = i & 15;
            CP16(ks + (uint32_t)(r * APH_ + w * 4) * 4, Kg + (size_t)(j0 + r) * DH_ + w * 8);
            CP16(vs + (uint32_t)(r * APH_ + w * 4) * 4, Vg + (size_t)(j0 + r) * DH_ + w * 8);
        }
        CP_COMMIT();
    };

    copyKV(0, 0);

    float o[16][4];
    #pragma unroll
    for (int ni = 0; ni < 16; ni++)
        #pragma unroll
        for (int c = 0; c < 4; c++) o[ni][c] = 0.f;
    float mA = -1e30f, mB = -1e30f, lA = 0.f, lB = 0.f;

    for (int it = 0; it < S_ / 128; it++) {
        int buf = it & 1;
        __syncthreads();
        if (it + 1 < S_ / 128) {
            copyKV((it + 1) * 128, buf ^ 1);
            CP_WAIT1();
        } else {
            CP_WAIT0();
        }
        __syncthreads();

        uint32_t KsAddr = sbase + (uint32_t)((KS_OFF + buf * ATILE_) * 4);
        uint32_t VtAddr = sbase + (uint32_t)((VT_OFF + buf * ATILE_) * 4);

        float sf[16][4];
        #pragma unroll
        for (int ni = 0; ni < 16; ni++)
            #pragma unroll
            for (int c = 0; c < 4; c++) sf[ni][c] = 0.f;

        #pragma unroll
        for (int ks = 0; ks < 8; ks++) {
            uint32_t kb = (uint32_t)(ks * 8);
            uint32_t a[4], b[16][2];
            ldsm4(QsAddr + (aRow * APH_ + kb + aCo) * 4, a);
            #pragma unroll
            for (int p = 0; p < 8; p++) {
                uint32_t r4v[4];
                ldsm4(KsAddr + ((bRow + p * 16) * APH_ + kb + bCo) * 4, r4v);
                b[2 * p][0] = r4v[0]; b[2 * p][1] = r4v[1];
                b[2 * p + 1][0] = r4v[2]; b[2 * p + 1][1] = r4v[3];
            }
            #pragma unroll
            for (int ni = 0; ni < 16; ni++)
                mma_f16(sf[ni], a, b[ni]);
        }

        float mxA = -1e30f, mxB = -1e30f;
        #pragma unroll
        for (int ni = 0; ni < 16; ni++) {
            mxA = fmaxf(mxA, fmaxf(sf[ni][0], sf[ni][1]));
            mxB = fmaxf(mxB, fmaxf(sf[ni][2], sf[ni][3]));
        }
        mxA = fmaxf(mxA, __shfl_xor_sync(0xffffffffu, mxA, 1));
        mxA = fmaxf(mxA, __shfl_xor_sync(0xffffffffu, mxA, 2));
        mxB = fmaxf(mxB, __shfl_xor_sync(0xffffffffu, mxB, 1));
        mxB = fmaxf(mxB, __shfl_xor_sync(0xffffffffu, mxB, 2));
        float mnA = fmaxf(mA, mxA), mnB = fmaxf(mB, mxB);
        float scA = __expf(mA - mnA), scB = __expf(mB - mnB);
        float sA = 0.f, sB = 0.f;
        int prA = (m0w + r4) * APH_;
        int prB = prA + 8 * APH_;
        #pragma unroll
        for (int ni = 0; ni < 16; ni++) {
            float e0 = __expf(sf[ni][0] - mnA);
            float e1 = __expf(sf[ni][1] - mnA);
            float e2 = __expf(sf[ni][2] - mnB);
            float e3 = __expf(sf[ni][3] - mnB);
            sA += e0 + e1; sB += e2 + e3;
            int cw = ni * 4 + c4;
            Ps[prA + cw] = pack_h2(e0, e1);
            Ps[prB + cw] = pack_h2(e2, e3);
        }
        sA += __shfl_xor_sync(0xffffffffu, sA, 1);
        sA += __shfl_xor_sync(0xffffffffu, sA, 2);
        sB += __shfl_xor_sync(0xffffffffu, sB, 1);
        sB += __shfl_xor_sync(0xffffffffu, sB, 2);
        lA = lA * scA + sA; lB = lB * scB + sB;
        mA = mnA; mB = mnB;
        #pragma unroll
        for (int ni = 0; ni < 16; ni++) {
            o[ni][0] *= scA; o[ni][1] *= scA;
            o[ni][2] *= scB; o[ni][3] *= scB;
        }
        __syncwarp();

        #pragma unroll
        for (int ks = 0; ks < 8; ks++) {
            uint32_t kb = (uint32_t)(ks * 8);
            uint32_t a[4], b[16][2];
            ldsm4(PsAddr + (aRow * APH_ + kb + aCo) * 4, a);
            #pragma unroll
            for (int p = 0; p < 8; p++) {
                uint32_t r4v[4];
                ldsm4t(VtAddr + ((ks * 16 + vRow) * APH_ + p * 8 + vCo) * 4, r4v);
                b[2 * p][0] = r4v[0]; b[2 * p][1] = r4v[1];
                b[2 * p + 1][0] = r4v[2]; b[2 * p + 1][1] = r4v[3];
            }
            #pragma unroll
            for (int ni = 0; ni < 16; ni++)
                mma_f16(o[ni], a, b[ni]);
        }
    }

    float invA = 1.f / lA, invB = 1.f / lB;
    int bb = bh >> 3, h = bh & 7;
    int sApos = q0 + m0w + r4;
    int tA = bb * S_ + sApos;
    int tB = tA + 8;
    const float* gpA = g_go + (size_t)tA * GE_ + h * 4;
    const float* gpB = g_go + (size_t)tB * GE_ + h * 4;
    float gA[4], gB[4];
    #pragma unroll
    for (int e = 0; e < 4; e++) { gA[e] = gpA[e]; gB[e] = gpB[e]; }
    __half* baseA = g_aexp + (size_t)tA * KEXP_ + h * 512;
    __half* baseB = g_aexp + (size_t)tB * KEXP_ + h * 512;
    #pragma unroll
    for (int ni = 0; ni < 16; ni++) {
        int cc = ni * 8 + c4 * 2;
        float ax = o[ni][0] * invA, ay = o[ni][1] * invA;
        float bx = o[ni][2] * invB, by = o[ni][3] * invB;
        #pragma unroll
        for (int e = 0; e < 4; e++) {
            *(__half2*)(baseA + e * 128 + cc) = __floats2half2_rn(ax * gA[e], ay * gA[e]);
            *(__half2*)(baseB + e * 128 + cc) = __floats2half2_rn(bx * gB[e], by * gB[e]);
        }
    }
}

// ---------------------------------------------------------------------------
extern "C" void kernel_launch(void* const* d_in, const int* in_sizes, int n_in,
                              void* d_out, int out_size) {
    const float* q_src = (const float*)d_in[0];
    const float* k_src = (const float*)d_in[1];
    const float* v_src = (const float*)d_in[2];
    const float* Wq    = (const float*)d_in[3];
    const float* Wk    = (const float*)d_in[4];
    const float* Wv    = (const float*)d_in[5];
    const float* Wo    = (const float*)d_in[6];
    const float* sel_v = (const float*)d_in[7];
    const float* sel_o = (const float*)d_in[8];
    float* outp = (float*)d_out;

    cudaFuncSetAttribute(attn_tc_kernel, cudaFuncAttributeMaxDynamicSharedMemorySize, ATTN_SMEM);
    cudaFuncSetAttribute(gemm_qkv, cudaFuncAttributeMaxDynamicSharedMemorySize, GSMEM_BYTES);
    cudaFuncSetAttribute(gemm_out, cudaFuncAttributeMaxDynamicSharedMemorySize, GSMEM_BYTES);
    cudaFuncSetAttribute(router_kernel, cudaFuncAttributeMaxDynamicSharedMemorySize, RSMEM_BYTES);

    __half *gwoT;
    cudaGetSymbolAddress((void**)&gwoT, g_woT);

    const float scale = 0.29730177875068026f;  // 128^-0.25

    router_kernel<<<dim3(TOK_ / RT_, 2), 256, RSMEM_BYTES>>>(k_src, q_src, sel_v, sel_o);

    conv_all_kernel<<<(CVTOT_ + 255) / 256, 256>>>(q_src, k_src, v_src, Wq, Wk);

    transpose_wv_kernel<<<dim3(DH_ / 32, D_ / 32, GE_), dim3(32, 8)>>>(Wv);
    transpose_kernel<<<dim3(D_ / 32, KEXP_ / 32, 1), dim3(32, 8)>>>(Wo, gwoT, KEXP_, D_);

    // fused q-proj / k-proj / gated-V GEMM (768 blocks, one tail)
    gemm_qkv<<<dim3(24, TOK_ / 128), 512, GSMEM_BYTES>>>(scale);

    attn_tc_kernel<<<dim3(S_ / 128, B_ * H_), 256, ATTN_SMEM>>>();

    // out: M=4096, N=1024, K=4096 -> fp32
    gemm_out<<<dim3(D_ / 256, TOK_ / 128), 512, GSMEM_BYTES>>>(outp);
}